// round 14
// baseline (speedup 1.0000x reference)
#include <cuda_runtime.h>

#define F 96
#define C4 24               // float4 chunks per feature row
#define CAPN 50240          // node capacity (N = 50000)
#define FULLM 0xffffffffu
#define ET 64               // edges per scatter tile
#define XPAD 100            // padded k-stride for x tile in smem
#define GR 64               // gemm rows per block

// ---- scratch (__device__ globals; accessed ONLY by name in device code) ----
__device__ int    g_degi[CAPN];        // zeroed statically; re-zeroed in gemm1
__device__ float  g_dinv[CAPN];
__device__ float  g_wt[3][F * F];      // W1,W2a,W2b transposed: [col][k]
__device__ float4 g_agg1[CAPN * C4];   // scatter target 1
__device__ float4 g_h1s [CAPN * C4];   // relu((A x)@W1 + b1)   (unscaled)
__device__ float4 g_agg2[CAPN * C4];   // scatter target 2

template <int SEL> __device__ __forceinline__ float4* buf();
template <> __device__ __forceinline__ float4* buf<1>() { return g_agg1; }
template <> __device__ __forceinline__ float4* buf<3>() { return g_agg2; }

__device__ __forceinline__ void red4(float4* p, float4 v) { atomicAdd(p, v); }

// packed f32x2 fma: a += v * m  (lanes independent)
__device__ __forceinline__ void fma2(unsigned long long& a,
                                     unsigned long long v,
                                     unsigned long long m) {
    asm volatile("fma.rn.f32x2 %0, %1, %2, %0;" : "+l"(a) : "l"(v), "l"(m));
}
__device__ __forceinline__ float sum2(unsigned long long a) {
    float2 f = *reinterpret_cast<float2*>(&a);
    return f.x + f.y;
}

// ---------------------------------------------------------------------------
// launch 0: degree by dst (warp-aggregated for contiguous hub edges)
//           + transpose the 3 weight matrices into g_wt (first 27648 threads)
// ---------------------------------------------------------------------------
__global__ void deg_kernel(const int* __restrict__ dst,
                           const float* __restrict__ W1,
                           const float* __restrict__ W2a,
                           const float* __restrict__ W2b, int E) {
    int e = blockIdx.x * blockDim.x + threadIdx.x;

    if (e < 3 * F * F) {                   // weight transpose side-job
        int m = e / (F * F), r = e % (F * F);
        int k = r / F, c = r % F;
        const float* Wm = (m == 0) ? W1 : (m == 1) ? W2a : W2b;
        g_wt[m][c * F + k] = Wm[k * F + c];
    }

    bool valid = e < E;
    int d = valid ? dst[e] : -1;
    int d0 = __shfl_sync(FULLM, d, 0);
    unsigned bal = __ballot_sync(FULLM, valid && d == d0);
    if (bal == FULLM) {
        if ((threadIdx.x & 31) == 0) atomicAdd(&g_degi[d0], 32);
    } else if (valid) {
        atomicAdd(&g_degi[d], 1);
    }
}

// ---------------------------------------------------------------------------
// launch 1: dinv from degi + zero both agg buffers
// ---------------------------------------------------------------------------
__global__ void initz_kernel(int N) {
    int i = blockIdx.x * blockDim.x + threadIdx.x;   // float4 index
    int n4 = N * C4;
    if (i >= n4) return;
    float4 z = make_float4(0.f, 0.f, 0.f, 0.f);
    g_agg1[i] = z;
    g_agg2[i] = z;
    if (i < N) {
        int dg = g_degi[i];
        g_dinv[i] = dg > 0 ? rsqrtf(fmaxf((float)dg, 1.f)) : 0.f;
    }
}

// ---------------------------------------------------------------------------
// Scatter: agg[dst] += dinv[src] * feat[src]
// 192 threads = 8 edge-slots x 24 chunks; 64-edge tiles staged in smem
// (src, dst, dinv[src]). Uniform-dst (hub) tiles -> 1 atomic per chunk.
// USEH1: feat = g_h1s (by name); else feat = xfeat param (harness pointer).
// ---------------------------------------------------------------------------
template <bool USEH1, int OUT>
__global__ void __launch_bounds__(192) scatter_kernel(
        const int* __restrict__ src, const int* __restrict__ dst,
        const float4* __restrict__ xfeat, int E) {
    const float4* __restrict__ feat = USEH1 ? g_h1s : xfeat;
    float4* __restrict__ agg = buf<OUT>();

    const int t = threadIdx.x;
    const int c = t % C4;               // chunk 0..23
    const int g = t / C4;               // edge slot 0..7
    __shared__ int    ss[ET], sd[ET];
    __shared__ float  sn[ET];
    __shared__ int    s_uni;
    __shared__ float4 sred[192];

    const int base = blockIdx.x * ET;
    const int m = min(ET, E - base);

    if (t == 0) s_uni = (m == ET) ? 1 : 0;
    if (t < m) {
        int s = src[base + t];
        ss[t] = s;
        sd[t] = dst[base + t];
        sn[t] = g_dinv[s];
    }
    __syncthreads();
    if (t < m && sd[t] != sd[0]) s_uni = 0;
    __syncthreads();

    if (s_uni) {
        float4 acc = make_float4(0.f, 0.f, 0.f, 0.f);
#pragma unroll
        for (int r = 0; r < 8; r++) {
            int j = r * 8 + g;
            float nm = sn[j];
            float4 v = __ldg(feat + (size_t)ss[j] * C4 + c);
            acc.x = fmaf(nm, v.x, acc.x); acc.y = fmaf(nm, v.y, acc.y);
            acc.z = fmaf(nm, v.z, acc.z); acc.w = fmaf(nm, v.w, acc.w);
        }
        sred[t] = acc;
        __syncthreads();
        if (g == 0) {
#pragma unroll
            for (int k = 1; k < 8; k++) {
                float4 v = sred[k * C4 + c];
                acc.x += v.x; acc.y += v.y; acc.z += v.z; acc.w += v.w;
            }
            red4(agg + (size_t)sd[0] * C4 + c, acc);
        }
    } else {
#pragma unroll
        for (int r = 0; r < 8; r++) {
            int j = r * 8 + g;
            if (j < m) {
                float nm = sn[j];
                float4 v = __ldg(feat + (size_t)ss[j] * C4 + c);
                v.x *= nm; v.y *= nm; v.z *= nm; v.w *= nm;
                red4(agg + (size_t)sd[j] * C4 + c, v);
            }
        }
    }
}

// ---------------------------------------------------------------------------
// Register-tiled GEMM: block = 64 rows x 96 cols, 256 threads.
// Thread tile = 4 rows x 6 cols, accumulators k-parity packed (f32x2).
// W read via __ldg from g_wt[.] (36KB, L1-resident); x tile in static smem.
// ---------------------------------------------------------------------------
template <int IN>
__device__ __forceinline__ void load_xtile(float* xs, int row0, int N, int t) {
    const float4* __restrict__ a = buf<IN>();
    for (int i = t; i < GR * C4; i += 256) {     // float4 index within tile
        int r = i / C4, c4 = i % C4;
        int row = row0 + r;
        float4 v = make_float4(0.f, 0.f, 0.f, 0.f);
        if (row < N) {
            float dv = g_dinv[row];
            v = a[(size_t)row * C4 + c4];
            v.x *= dv; v.y *= dv; v.z *= dv; v.w *= dv;
        }
        *(float4*)&xs[r * XPAD + c4 * 4] = v;
    }
}

// 4 rows x 6 cols product; acc[r*6+c] packed over k-parity
__device__ __forceinline__ void mmkern(const float* __restrict__ wt,
                                       const float* xs,
                                       int r0, int col0,
                                       unsigned long long acc[24]) {
#pragma unroll
    for (int k0 = 0; k0 < F; k0 += 4) {
        ulonglong2 xv[4];
#pragma unroll
        for (int r = 0; r < 4; r++)
            xv[r] = *(const ulonglong2*)&xs[(r0 + r) * XPAD + k0];
#pragma unroll
        for (int c = 0; c < 6; c++) {
            ulonglong2 wv = __ldg((const ulonglong2*)&wt[(col0 + c) * F + k0]);
#pragma unroll
            for (int r = 0; r < 4; r++) {
                fma2(acc[r * 6 + c], xv[r].x, wv.x);
                fma2(acc[r * 6 + c], xv[r].y, wv.y);
            }
        }
    }
}

// ---------------------------------------------------------------------------
// launch 3: gemm1: g_h1s = relu((g_agg1 .* dinv) @ W1 + b1)   (unscaled out)
// Also re-zeroes g_degi for the next graph replay.
// ---------------------------------------------------------------------------
__global__ void __launch_bounds__(256, 3) gemm1_kernel(
        const float* __restrict__ b, int N) {
    __shared__ __align__(16) float xs[GR * XPAD];
    const int t = threadIdx.x;
    {   // replay-reset of degree counters, piggybacked
        int gi = blockIdx.x * 256 + t;
        if (gi < N) g_degi[gi] = 0;
    }
    const int row0 = blockIdx.x * GR;
    load_xtile<1>(xs, row0, N, t);
    __syncthreads();

    const int col0 = (t & 15) * 6;
    const int r0 = (t >> 4) * 4;
    unsigned long long acc[24] = {};
    mmkern(g_wt[0], xs, r0, col0, acc);

#pragma unroll
    for (int r = 0; r < 4; r++) {
        int row = row0 + r0 + r;
        if (row < N) {
            float* o = (float*)g_h1s + (size_t)row * F + col0;
#pragma unroll
            for (int q = 0; q < 3; q++) {
                float2 v;
                v.x = fmaxf(sum2(acc[r*6 + q*2 + 0]) + b[col0 + q*2 + 0], 0.f);
                v.y = fmaxf(sum2(acc[r*6 + q*2 + 1]) + b[col0 + q*2 + 1], 0.f);
                *(float2*)&o[q * 2] = v;
            }
        }
    }
}

// ---------------------------------------------------------------------------
// launch 5: dual GEMM via gridDim.y: y=0 -> mu (W2a), y=1 -> logstd (W2b)
// ---------------------------------------------------------------------------
__global__ void __launch_bounds__(256, 3) gemm2_kernel(
        const float* __restrict__ ba, const float* __restrict__ bb,
        float* __restrict__ out, int N) {
    __shared__ __align__(16) float xs[GR * XPAD];
    const int t = threadIdx.x;
    const int row0 = blockIdx.x * GR;
    const int phase = blockIdx.y;
    const float* __restrict__ wt = g_wt[1 + phase];
    const float* __restrict__ b = phase ? bb : ba;
    float* __restrict__ o = out + (phase ? (size_t)N * F : 0);

    load_xtile<3>(xs, row0, N, t);
    __syncthreads();

    const int col0 = (t & 15) * 6;
    const int r0 = (t >> 4) * 4;
    unsigned long long acc[24] = {};
    mmkern(wt, xs, r0, col0, acc);

#pragma unroll
    for (int r = 0; r < 4; r++) {
        int row = row0 + r0 + r;
        if (row < N) {
            size_t off = (size_t)row * F + col0;
#pragma unroll
            for (int q = 0; q < 3; q++) {
                float2 v;
                v.x = sum2(acc[r*6 + q*2 + 0]) + b[col0 + q*2 + 0];
                v.y = sum2(acc[r*6 + q*2 + 1]) + b[col0 + q*2 + 1];
                *(float2*)&o[off + q * 2] = v;
            }
        }
    }
}

// ---------------------------------------------------------------------------
// inputs: x, W1, b1, W2a, b2a, W2b, b2b, edge_index[2,E]
// output: concat(mu [N,F], logstd [N,F])
//
// A_norm = D^-1/2 A D^-1/2 and GCN linearity give:
//   GCN(x) = (dinv .* (A @ (dinv .* x))) @ W + b
// -> scatter multiplies by dinv[src] in-flight; GEMM load scales by dinv[row].
// NOTE: no __device__ symbol is ever passed from host (ATS shadow-addr trap).
// ---------------------------------------------------------------------------
extern "C" void kernel_launch(void* const* d_in, const int* in_sizes, int n_in,
                              void* d_out, int out_size) {
    const float* x   = (const float*)d_in[0];
    const float* W1  = (const float*)d_in[1];
    const float* b1  = (const float*)d_in[2];
    const float* W2a = (const float*)d_in[3];
    const float* b2a = (const float*)d_in[4];
    const float* W2b = (const float*)d_in[5];
    const float* b2b = (const float*)d_in[6];
    const int*   ei  = (const int*)d_in[7];

    const int N = in_sizes[0] / F;
    const int E = in_sizes[7] / 2;
    const int* src = ei;
    const int* dst = ei + E;
    float* out = (float*)d_out;

    const int TB = 256;
    int eg  = (E + TB - 1) / TB;
    int f4g = (N * C4 + TB - 1) / TB;
    int sg  = (E + ET - 1) / ET;
    int gg  = (N + GR - 1) / GR;

    deg_kernel  <<<eg, TB>>>(dst, W1, W2a, W2b, E);        // 0 (+W transpose)
    initz_kernel<<<f4g, TB>>>(N);                          // 1
    scatter_kernel<false, 1><<<sg, 192>>>(src, dst,
                               (const float4*)x, E);       // 2: x   -> agg1
    gemm1_kernel<<<gg, TB>>>(b1, N);                       // 3: -> h1s (+deg reset)
    scatter_kernel<true, 3><<<sg, 192>>>(src, dst, nullptr, E); // 4: h1s -> agg2
    gemm2_kernel<<<dim3(gg, 2), TB>>>(b2a, b2b, out, N);   // 5: mu + logstd
}

// round 15
// speedup vs baseline: 2.0072x; 2.0072x over previous
#include <cuda_runtime.h>

#define F 96
#define C4 24               // float4 chunks per feature row
#define CAPN 50240          // node capacity (N = 50000)
#define FULLM 0xffffffffu
#define ET 64               // edges per scatter tile
#define GR 64               // gemm rows per block

// swizzled smem offsets (floats); both keep 16B alignment for k%4==0
#define WTOFF(j, k) ((j) * 100 + ((j) / 12) * 4 + (k))
#define XSOFF(r, k) ((r) * 100 + ((r) / 4) * 4 + (k))
#define WT_FLOATS (WTOFF(95, 96) + 4)          // 9628
#define XS_FLOATS (XSOFF(63, 96) + 4)          // 6460
#define SMEMSZ ((WT_FLOATS + XS_FLOATS) * 4)   // ~64.4KB

// ---- scratch (__device__ globals; accessed ONLY by name in device code) ----
__device__ int    g_degi[CAPN];        // zeroed statically; re-zeroed in gemm1
__device__ float  g_dinv[CAPN];
__device__ float4 g_agg1[CAPN * C4];   // scatter target 1
__device__ float4 g_h1s [CAPN * C4];   // relu((A x)@W1 + b1)  (unscaled)
__device__ float4 g_agg2[CAPN * C4];   // scatter target 2

template <int SEL> __device__ __forceinline__ float4* buf();
template <> __device__ __forceinline__ float4* buf<1>() { return g_agg1; }
template <> __device__ __forceinline__ float4* buf<3>() { return g_agg2; }

__device__ __forceinline__ void red4(float4* p, float4 v) { atomicAdd(p, v); }

// packed f32x2 fma: a += v * m  (lanes independent)
__device__ __forceinline__ void fma2(unsigned long long& a,
                                     unsigned long long v,
                                     unsigned long long m) {
    asm volatile("fma.rn.f32x2 %0, %1, %2, %0;" : "+l"(a) : "l"(v), "l"(m));
}
__device__ __forceinline__ float sum2(unsigned long long a) {
    float2 f = *reinterpret_cast<float2*>(&a);
    return f.x + f.y;
}

// ---------------------------------------------------------------------------
// launch 0: degree by dst; warp-aggregated for contiguous hub edges
// ---------------------------------------------------------------------------
__global__ void deg_kernel(const int* __restrict__ dst, int E) {
    int e = blockIdx.x * blockDim.x + threadIdx.x;
    bool valid = e < E;
    int d = valid ? dst[e] : -1;
    int d0 = __shfl_sync(FULLM, d, 0);
    unsigned bal = __ballot_sync(FULLM, valid && d == d0);
    if (bal == FULLM) {
        if ((threadIdx.x & 31) == 0) atomicAdd(&g_degi[d0], 32);
    } else if (valid) {
        atomicAdd(&g_degi[d], 1);
    }
}

// ---------------------------------------------------------------------------
// launch 1: dinv from degi + zero both agg buffers
// ---------------------------------------------------------------------------
__global__ void initz_kernel(int N) {
    int i = blockIdx.x * blockDim.x + threadIdx.x;   // float4 index
    int n4 = N * C4;
    if (i >= n4) return;
    float4 z = make_float4(0.f, 0.f, 0.f, 0.f);
    g_agg1[i] = z;
    g_agg2[i] = z;
    if (i < N) {
        int dg = g_degi[i];
        g_dinv[i] = dg > 0 ? rsqrtf(fmaxf((float)dg, 1.f)) : 0.f;
    }
}

// ---------------------------------------------------------------------------
// Scatter: agg[dst] += dinv[src] * feat[src]
// 192 threads = 8 edge-slots x 24 chunks; 64-edge tiles staged in smem
// (src, dst, dinv[src]). Uniform-dst (hub) tiles -> 1 atomic per chunk.
// ---------------------------------------------------------------------------
template <bool USEH1, int OUT>
__global__ void __launch_bounds__(192) scatter_kernel(
        const int* __restrict__ src, const int* __restrict__ dst,
        const float4* __restrict__ xfeat, int E) {
    const float4* __restrict__ feat = USEH1 ? g_h1s : xfeat;
    float4* __restrict__ agg = buf<OUT>();

    const int t = threadIdx.x;
    const int c = t % C4;               // chunk 0..23
    const int g = t / C4;               // edge slot 0..7
    __shared__ int    ss[ET], sd[ET];
    __shared__ float  sn[ET];
    __shared__ int    s_uni;
    __shared__ float4 sred[192];

    const int base = blockIdx.x * ET;
    const int m = min(ET, E - base);

    if (t == 0) s_uni = (m == ET) ? 1 : 0;
    if (t < m) {
        int s = src[base + t];
        ss[t] = s;
        sd[t] = dst[base + t];
        sn[t] = g_dinv[s];
    }
    __syncthreads();
    if (t < m && sd[t] != sd[0]) s_uni = 0;
    __syncthreads();

    if (s_uni) {
        float4 acc = make_float4(0.f, 0.f, 0.f, 0.f);
#pragma unroll
        for (int r = 0; r < 8; r++) {
            int j = r * 8 + g;
            float nm = sn[j];
            float4 v = __ldg(feat + (size_t)ss[j] * C4 + c);
            acc.x = fmaf(nm, v.x, acc.x); acc.y = fmaf(nm, v.y, acc.y);
            acc.z = fmaf(nm, v.z, acc.z); acc.w = fmaf(nm, v.w, acc.w);
        }
        sred[t] = acc;
        __syncthreads();
        if (g == 0) {
#pragma unroll
            for (int k = 1; k < 8; k++) {
                float4 v = sred[k * C4 + c];
                acc.x += v.x; acc.y += v.y; acc.z += v.z; acc.w += v.w;
            }
            red4(agg + (size_t)sd[0] * C4 + c, acc);
        }
    } else {
#pragma unroll
        for (int r = 0; r < 8; r++) {
            int j = r * 8 + g;
            if (j < m) {
                float nm = sn[j];
                float4 v = __ldg(feat + (size_t)ss[j] * C4 + c);
                v.x *= nm; v.y *= nm; v.z *= nm; v.w *= nm;
                red4(agg + (size_t)sd[j] * C4 + c, v);
            }
        }
    }
}

// ---------------------------------------------------------------------------
// Register-tiled GEMM: block = 64 rows x 96 cols, 128 threads.
// Thread tile = 4 rows x 12 cols; rowg = t>>3 (16), colg = t&7 (8).
// Swizzled smem layouts make W-LDS (8 distinct slots) and x-LDS (4 distinct)
// single-wavefront. Accumulators k-parity packed (f32x2).
// ---------------------------------------------------------------------------
__device__ __forceinline__ void load_wt(float* Wt, const float* __restrict__ W,
                                        int t) {
    const float4* __restrict__ W4 = (const float4*)W;
    for (int i = t; i < F * C4; i += 128) {      // k = i/C4, col group = i%C4
        int k = i / C4, cg = i % C4;
        float4 w = __ldg(W4 + i);
        int j = cg * 4;
        Wt[WTOFF(j + 0, k)] = w.x;
        Wt[WTOFF(j + 1, k)] = w.y;
        Wt[WTOFF(j + 2, k)] = w.z;
        Wt[WTOFF(j + 3, k)] = w.w;
    }
}

template <int IN>
__device__ __forceinline__ void load_xtile(float* xs, int row0, int N, int t) {
    const float4* __restrict__ a = buf<IN>();
    for (int i = t; i < GR * C4; i += 128) {     // float4 index within tile
        int r = i / C4, c4 = i % C4;
        int row = row0 + r;
        float4 v = make_float4(0.f, 0.f, 0.f, 0.f);
        if (row < N) {
            float dv = g_dinv[row];
            v = a[(size_t)row * C4 + c4];
            v.x *= dv; v.y *= dv; v.z *= dv; v.w *= dv;
        }
        *(float4*)&xs[XSOFF(r, c4 * 4)] = v;
    }
}

// 4 rows x 12 cols product; acc[r*12+c] packed over k-parity
__device__ __forceinline__ void mmkern(const float* Wt, const float* xs,
                                       int rowg, int colg,
                                       unsigned long long acc[48]) {
    const int r0 = rowg * 4;
    const int col0 = colg * 12;
#pragma unroll 4
    for (int k0 = 0; k0 < F; k0 += 4) {
        ulonglong2 xv[4];
#pragma unroll
        for (int r = 0; r < 4; r++)
            xv[r] = *(const ulonglong2*)&xs[XSOFF(r0 + r, k0)];
#pragma unroll
        for (int c = 0; c < 12; c++) {
            ulonglong2 wv = *(const ulonglong2*)&Wt[WTOFF(col0 + c, k0)];
#pragma unroll
            for (int r = 0; r < 4; r++) {
                fma2(acc[r * 12 + c], xv[r].x, wv.x);
                fma2(acc[r * 12 + c], xv[r].y, wv.y);
            }
        }
    }
}

// ---------------------------------------------------------------------------
// launch 3: gemm1: g_h1s = relu((g_agg1 .* dinv) @ W1 + b1)   (unscaled out)
// Also re-zeroes g_degi for the next graph replay.
// ---------------------------------------------------------------------------
__global__ void __launch_bounds__(128) gemm1_kernel(
        const float* __restrict__ W, const float* __restrict__ b, int N) {
    extern __shared__ float sm[];
    float* Wt = sm;
    float* xs = sm + WT_FLOATS;
    const int t = threadIdx.x;
    {   // replay-reset of degree counters, piggybacked
        int gi = blockIdx.x * 128 + t;
        if (gi < N) g_degi[gi] = 0;
    }
    const int row0 = blockIdx.x * GR;
    load_wt(Wt, W, t);
    load_xtile<1>(xs, row0, N, t);
    __syncthreads();

    const int rowg = t >> 3, colg = t & 7;
    unsigned long long acc[48] = {};
    mmkern(Wt, xs, rowg, colg, acc);

    const int col0 = colg * 12;
#pragma unroll
    for (int r = 0; r < 4; r++) {
        int row = row0 + rowg * 4 + r;
        if (row < N) {
            float* o = (float*)g_h1s + (size_t)row * F + col0;
#pragma unroll
            for (int q = 0; q < 3; q++) {
                float4 v;
                v.x = fmaxf(sum2(acc[r*12 + q*4 + 0]) + b[col0 + q*4 + 0], 0.f);
                v.y = fmaxf(sum2(acc[r*12 + q*4 + 1]) + b[col0 + q*4 + 1], 0.f);
                v.z = fmaxf(sum2(acc[r*12 + q*4 + 2]) + b[col0 + q*4 + 2], 0.f);
                v.w = fmaxf(sum2(acc[r*12 + q*4 + 3]) + b[col0 + q*4 + 3], 0.f);
                *(float4*)&o[q * 4] = v;
            }
        }
    }
}

// ---------------------------------------------------------------------------
// launch 5: dual GEMM via gridDim.y: y=0 -> mu (W2a), y=1 -> logstd (W2b)
// ---------------------------------------------------------------------------
__global__ void __launch_bounds__(128) gemm2_kernel(
        const float* __restrict__ Wa, const float* __restrict__ ba,
        const float* __restrict__ Wb, const float* __restrict__ bb,
        float* __restrict__ out, int N) {
    extern __shared__ float sm[];
    float* Wt = sm;
    float* xs = sm + WT_FLOATS;
    const int t = threadIdx.x;
    const int row0 = blockIdx.x * GR;
    const int phase = blockIdx.y;
    const float* __restrict__ W = phase ? Wb : Wa;
    const float* __restrict__ b = phase ? bb : ba;
    float* __restrict__ o = out + (phase ? (size_t)N * F : 0);

    load_wt(Wt, W, t);
    load_xtile<3>(xs, row0, N, t);
    __syncthreads();

    const int rowg = t >> 3, colg = t & 7;
    unsigned long long acc[48] = {};
    mmkern(Wt, xs, rowg, colg, acc);

    const int col0 = colg * 12;
#pragma unroll
    for (int r = 0; r < 4; r++) {
        int row = row0 + rowg * 4 + r;
        if (row < N) {
            size_t off = (size_t)row * F + col0;
#pragma unroll
            for (int q = 0; q < 3; q++) {
                float4 v;
                v.x = sum2(acc[r*12 + q*4 + 0]) + b[col0 + q*4 + 0];
                v.y = sum2(acc[r*12 + q*4 + 1]) + b[col0 + q*4 + 1];
                v.z = sum2(acc[r*12 + q*4 + 2]) + b[col0 + q*4 + 2];
                v.w = sum2(acc[r*12 + q*4 + 3]) + b[col0 + q*4 + 3];
                *(float4*)&o[off + q * 4] = v;
            }
        }
    }
}

// ---------------------------------------------------------------------------
// inputs: x, W1, b1, W2a, b2a, W2b, b2b, edge_index[2,E]
// output: concat(mu [N,F], logstd [N,F])
//
// A_norm = D^-1/2 A D^-1/2 and GCN linearity give:
//   GCN(x) = (dinv .* (A @ (dinv .* x))) @ W + b
// -> scatter multiplies by dinv[src] in-flight; GEMM load scales by dinv[row].
// NOTE: no __device__ symbol is ever passed from host (ATS shadow-addr trap).
// ---------------------------------------------------------------------------
extern "C" void kernel_launch(void* const* d_in, const int* in_sizes, int n_in,
                              void* d_out, int out_size) {
    const float* x   = (const float*)d_in[0];
    const float* W1  = (const float*)d_in[1];
    const float* b1  = (const float*)d_in[2];
    const float* W2a = (const float*)d_in[3];
    const float* b2a = (const float*)d_in[4];
    const float* W2b = (const float*)d_in[5];
    const float* b2b = (const float*)d_in[6];
    const int*   ei  = (const int*)d_in[7];

    const int N = in_sizes[0] / F;
    const int E = in_sizes[7] / 2;
    const int* src = ei;
    const int* dst = ei + E;
    float* out = (float*)d_out;

    // >48KB dynamic smem opt-in + full shared carveout for gemm kernels
    cudaFuncSetAttribute(gemm1_kernel,
        cudaFuncAttributeMaxDynamicSharedMemorySize, SMEMSZ);
    cudaFuncSetAttribute(gemm2_kernel,
        cudaFuncAttributeMaxDynamicSharedMemorySize, SMEMSZ);
    cudaFuncSetAttribute(gemm1_kernel,
        cudaFuncAttributePreferredSharedMemoryCarveout, 100);
    cudaFuncSetAttribute(gemm2_kernel,
        cudaFuncAttributePreferredSharedMemoryCarveout, 100);

    const int TB = 256;
    int eg  = (E + TB - 1) / TB;
    int f4g = (N * C4 + TB - 1) / TB;
    int sg  = (E + ET - 1) / ET;
    int gg  = (N + GR - 1) / GR;

    deg_kernel  <<<eg, TB>>>(dst, E);                       // 0
    initz_kernel<<<f4g, TB>>>(N);                           // 1
    scatter_kernel<false, 1><<<sg, 192>>>(src, dst,
                               (const float4*)x, E);        // 2: x   -> agg1
    gemm1_kernel<<<gg, 128, SMEMSZ>>>(W1, b1, N);           // 3: -> h1s (+deg reset)
    scatter_kernel<true, 3><<<sg, 192>>>(src, dst, nullptr, E); // 4: h1s -> agg2
    gemm2_kernel<<<dim3(gg, 2), 128, SMEMSZ>>>(W2a, b2a, W2b, b2b, out, N); // 5
}

// round 16
// speedup vs baseline: 2.1122x; 1.0523x over previous
#include <cuda_runtime.h>

#define F 96
#define C4 24               // float4 chunks per feature row
#define CAPN 50240          // node capacity (N = 50000)
#define FULLM 0xffffffffu
#define ET 64               // edges per scatter tile
#define GR 64               // gemm rows per block

// swizzled smem layout for a 48-column half of W: [jlocal][k]
// lane stride (6 cols) = 604 floats = 151 16B-units == 7 (mod 8) -> conflict-free
#define WTOFF(j, k) ((j) * 100 + ((j) / 6) * 4 + (k))
#define WT_FLOATS (WTOFF(47, 96) + 4)          // 4828 floats ~ 19.3KB

// ---- scratch (__device__ globals; accessed ONLY by name in device code) ----
__device__ int    g_degi[CAPN];        // zeroed statically; re-zeroed in gemm1
__device__ float  g_dinv[CAPN];
__device__ float4 g_agg1[CAPN * C4];   // scatter target 1
__device__ float4 g_h1s [CAPN * C4];   // relu((A x)@W1 + b1)  (unscaled)
__device__ float4 g_agg2[CAPN * C4];   // scatter target 2

template <int SEL> __device__ __forceinline__ float4* buf();
template <> __device__ __forceinline__ float4* buf<1>() { return g_agg1; }
template <> __device__ __forceinline__ float4* buf<3>() { return g_agg2; }

__device__ __forceinline__ void red4(float4* p, float4 v) { atomicAdd(p, v); }

// packed f32x2 fma: a += v * m  (lanes independent)
__device__ __forceinline__ void fma2(unsigned long long& a,
                                     unsigned long long v,
                                     unsigned long long m) {
    asm volatile("fma.rn.f32x2 %0, %1, %2, %0;" : "+l"(a) : "l"(v), "l"(m));
}
__device__ __forceinline__ float sum2(unsigned long long a) {
    float2 f = *reinterpret_cast<float2*>(&a);
    return f.x + f.y;
}

// ---------------------------------------------------------------------------
// launch 0: degree by dst; warp-aggregated for contiguous hub edges
// ---------------------------------------------------------------------------
__global__ void deg_kernel(const int* __restrict__ dst, int E) {
    int e = blockIdx.x * blockDim.x + threadIdx.x;
    bool valid = e < E;
    int d = valid ? dst[e] : -1;
    int d0 = __shfl_sync(FULLM, d, 0);
    unsigned bal = __ballot_sync(FULLM, valid && d == d0);
    if (bal == FULLM) {
        if ((threadIdx.x & 31) == 0) atomicAdd(&g_degi[d0], 32);
    } else if (valid) {
        atomicAdd(&g_degi[d], 1);
    }
}

// ---------------------------------------------------------------------------
// launch 1: dinv from degi + zero agg1 (agg2 is zeroed inside gemm1)
// ---------------------------------------------------------------------------
__global__ void initz_kernel(int N) {
    int i = blockIdx.x * blockDim.x + threadIdx.x;   // float4 index
    int n4 = N * C4;
    if (i >= n4) return;
    g_agg1[i] = make_float4(0.f, 0.f, 0.f, 0.f);
    if (i < N) {
        int dg = g_degi[i];
        g_dinv[i] = dg > 0 ? rsqrtf(fmaxf((float)dg, 1.f)) : 0.f;
    }
}

// ---------------------------------------------------------------------------
// Scatter: agg[dst] += dinv[src] * feat[src]
// 192 threads = 8 edge-slots x 24 chunks; 64-edge tiles staged in smem
// (src, dst, dinv[src]). Uniform-dst (hub) tiles -> 1 atomic per chunk.
// ---------------------------------------------------------------------------
template <bool USEH1, int OUT>
__global__ void __launch_bounds__(192) scatter_kernel(
        const int* __restrict__ src, const int* __restrict__ dst,
        const float4* __restrict__ xfeat, int E) {
    const float4* __restrict__ feat = USEH1 ? g_h1s : xfeat;
    float4* __restrict__ agg = buf<OUT>();

    const int t = threadIdx.x;
    const int c = t % C4;               // chunk 0..23
    const int g = t / C4;               // edge slot 0..7
    __shared__ int    ss[ET], sd[ET];
    __shared__ float  sn[ET];
    __shared__ int    s_uni;
    __shared__ float4 sred[192];

    const int base = blockIdx.x * ET;
    const int m = min(ET, E - base);

    if (t == 0) s_uni = (m == ET) ? 1 : 0;
    if (t < m) {
        int s = src[base + t];
        ss[t] = s;
        sd[t] = dst[base + t];
        sn[t] = g_dinv[s];
    }
    __syncthreads();
    if (t < m && sd[t] != sd[0]) s_uni = 0;
    __syncthreads();

    if (s_uni) {
        float4 acc = make_float4(0.f, 0.f, 0.f, 0.f);
#pragma unroll
        for (int r = 0; r < 8; r++) {
            int j = r * 8 + g;
            float nm = sn[j];
            float4 v = __ldg(feat + (size_t)ss[j] * C4 + c);
            acc.x = fmaf(nm, v.x, acc.x); acc.y = fmaf(nm, v.y, acc.y);
            acc.z = fmaf(nm, v.z, acc.z); acc.w = fmaf(nm, v.w, acc.w);
        }
        sred[t] = acc;
        __syncthreads();
        if (g == 0) {
#pragma unroll
            for (int k = 1; k < 8; k++) {
                float4 v = sred[k * C4 + c];
                acc.x += v.x; acc.y += v.y; acc.z += v.z; acc.w += v.w;
            }
            red4(agg + (size_t)sd[0] * C4 + c, acc);
        }
    } else {
#pragma unroll
        for (int r = 0; r < 8; r++) {
            int j = r * 8 + g;
            if (j < m) {
                float nm = sn[j];
                float4 v = __ldg(feat + (size_t)ss[j] * C4 + c);
                v.x *= nm; v.y *= nm; v.z *= nm; v.w *= nm;
                red4(agg + (size_t)sd[j] * C4 + c, v);
            }
        }
    }
}

// ---------------------------------------------------------------------------
// Register-tiled GEMM: block = 64 rows x 48 cols (half of W), 128 threads.
// Thread tile = 4 rows x 6 cols; rowg = t>>3 (16), colg = t&7 (8).
// W half in static smem (swizzled); x rows read directly via __ldg
// (4 distinct 16B addrs per warp load -> 1-2 wavefronts; L1-cached reuse).
// dinv[row] factored out of the dot product, applied in the epilogue.
// ---------------------------------------------------------------------------
__device__ __forceinline__ void load_wt_half(float* Wt,
                                             const float* __restrict__ W,
                                             int colhalf, int t) {
    const float4* __restrict__ W4 = (const float4*)W;
    for (int i = t; i < F * 12; i += 128) {      // k = i/12, local col grp = i%12
        int k = i / 12, cg = i % 12;
        float4 w = __ldg(W4 + k * C4 + colhalf * 12 + cg);
        int j = cg * 4;
        Wt[WTOFF(j + 0, k)] = w.x;
        Wt[WTOFF(j + 1, k)] = w.y;
        Wt[WTOFF(j + 2, k)] = w.z;
        Wt[WTOFF(j + 3, k)] = w.w;
    }
}

// 4 rows x 6 cols; acc[r*6+c] packed over k-parity; x via __ldg from agg rows
__device__ __forceinline__ void mmkern(const float* Wt,
                                       const float4* __restrict__ feat,
                                       int row0t, int colL0,
                                       unsigned long long acc[24]) {
#pragma unroll 4
    for (int k0 = 0; k0 < F; k0 += 4) {
        ulonglong2 xv[4];
#pragma unroll
        for (int r = 0; r < 4; r++)
            xv[r] = __ldg((const ulonglong2*)(feat + (size_t)(row0t + r) * C4
                                              + (k0 >> 2)));
#pragma unroll
        for (int c = 0; c < 6; c++) {
            ulonglong2 wv = *(const ulonglong2*)&Wt[WTOFF(colL0 + c, k0)];
#pragma unroll
            for (int r = 0; r < 4; r++) {
                fma2(acc[r * 6 + c], xv[r].x, wv.x);
                fma2(acc[r * 6 + c], xv[r].y, wv.y);
            }
        }
    }
}

// ---------------------------------------------------------------------------
// launch 3: gemm1: g_h1s = relu(dinv .* ((g_agg1) @ W1) + b1)   (unscaled out)
// gridDim = (gg, 2): y = column half. colhalf 0 also zeroes g_agg2 rows and
// re-zeroes g_degi for the next graph replay.
// ---------------------------------------------------------------------------
__global__ void __launch_bounds__(128) gemm1_kernel(
        const float* __restrict__ W, const float* __restrict__ b, int N) {
    __shared__ __align__(16) float Wt[WT_FLOATS];
    const int t = threadIdx.x;
    const int colhalf = blockIdx.y;
    const int row0 = blockIdx.x * GR;

    if (colhalf == 0) {
        // replay-reset of degree counters, piggybacked
        int gi = blockIdx.x * 128 + t;
        if (gi < N) g_degi[gi] = 0;
        // zero agg2 rows for this block (before scatter2 next launch)
        float4 z = make_float4(0.f, 0.f, 0.f, 0.f);
        for (int i = t; i < GR * C4; i += 128) {
            int row = row0 + i / C4;
            if (row < N) g_agg2[(size_t)row * C4 + (i % C4)] = z;
        }
    }
    load_wt_half(Wt, W, colhalf, t);
    __syncthreads();

    const int rowg = t >> 3, colg = t & 7;
    const int row0t = row0 + rowg * 4;
    const int colL0 = colg * 6;
    unsigned long long acc[24] = {};
    mmkern(Wt, g_agg1, row0t, colL0, acc);

    const int col0 = colhalf * 48 + colL0;
#pragma unroll
    for (int r = 0; r < 4; r++) {
        int row = row0t + r;
        if (row < N) {
            float dv = g_dinv[row];
            float* o = (float*)g_h1s + (size_t)row * F + col0;
#pragma unroll
            for (int q = 0; q < 3; q++) {
                float2 v;
                v.x = fmaxf(fmaf(dv, sum2(acc[r*6 + q*2 + 0]), b[col0 + q*2 + 0]), 0.f);
                v.y = fmaxf(fmaf(dv, sum2(acc[r*6 + q*2 + 1]), b[col0 + q*2 + 1]), 0.f);
                *(float2*)&o[q * 2] = v;
            }
        }
    }
}

// ---------------------------------------------------------------------------
// launch 5: dual GEMM, gridDim = (gg, 4): y&1 = column half, y>>1 = phase
// (0 -> mu / W2a, 1 -> logstd / W2b)
// ---------------------------------------------------------------------------
__global__ void __launch_bounds__(128) gemm2_kernel(
        const float* __restrict__ Wa, const float* __restrict__ ba,
        const float* __restrict__ Wb, const float* __restrict__ bb,
        float* __restrict__ out, int N) {
    __shared__ __align__(16) float Wt[WT_FLOATS];
    const int t = threadIdx.x;
    const int colhalf = blockIdx.y & 1;
    const int phase = blockIdx.y >> 1;
    const int row0 = blockIdx.x * GR;
    const float* __restrict__ W = phase ? Wb : Wa;
    const float* __restrict__ b = phase ? bb : ba;
    float* __restrict__ o = out + (phase ? (size_t)N * F : 0);

    load_wt_half(Wt, W, colhalf, t);
    __syncthreads();

    const int rowg = t >> 3, colg = t & 7;
    const int row0t = row0 + rowg * 4;
    const int colL0 = colg * 6;
    unsigned long long acc[24] = {};
    mmkern(Wt, g_agg2, row0t, colL0, acc);

    const int col0 = colhalf * 48 + colL0;
#pragma unroll
    for (int r = 0; r < 4; r++) {
        int row = row0t + r;
        if (row < N) {
            float dv = g_dinv[row];
            size_t off = (size_t)row * F + col0;
#pragma unroll
            for (int q = 0; q < 3; q++) {
                float2 v;
                v.x = fmaf(dv, sum2(acc[r*6 + q*2 + 0]), b[col0 + q*2 + 0]);
                v.y = fmaf(dv, sum2(acc[r*6 + q*2 + 1]), b[col0 + q*2 + 1]);
                *(float2*)&o[off + q * 2] = v;
            }
        }
    }
}

// ---------------------------------------------------------------------------
// inputs: x, W1, b1, W2a, b2a, W2b, b2b, edge_index[2,E]
// output: concat(mu [N,F], logstd [N,F])
//
// A_norm = D^-1/2 A D^-1/2 and GCN linearity give:
//   GCN(x) = (dinv .* (A @ (dinv .* x))) @ W + b
// -> scatter multiplies by dinv[src] in-flight; dst-side dinv is factored out
//    of the GEMM dot product and applied in the epilogue.
// NOTE: no __device__ symbol is ever passed from host (ATS shadow-addr trap).
// ---------------------------------------------------------------------------
extern "C" void kernel_launch(void* const* d_in, const int* in_sizes, int n_in,
                              void* d_out, int out_size) {
    const float* x   = (const float*)d_in[0];
    const float* W1  = (const float*)d_in[1];
    const float* b1  = (const float*)d_in[2];
    const float* W2a = (const float*)d_in[3];
    const float* b2a = (const float*)d_in[4];
    const float* W2b = (const float*)d_in[5];
    const float* b2b = (const float*)d_in[6];
    const int*   ei  = (const int*)d_in[7];

    const int N = in_sizes[0] / F;
    const int E = in_sizes[7] / 2;
    const int* src = ei;
    const int* dst = ei + E;
    float* out = (float*)d_out;

    const int TB = 256;
    int eg  = (E + TB - 1) / TB;
    int f4g = (N * C4 + TB - 1) / TB;
    int sg  = (E + ET - 1) / ET;
    int gg  = (N + GR - 1) / GR;

    deg_kernel  <<<eg, TB>>>(dst, E);                       // 0
    initz_kernel<<<f4g, TB>>>(N);                           // 1
    scatter_kernel<false, 1><<<sg, 192>>>(src, dst,
                               (const float4*)x, E);        // 2: x   -> agg1
    gemm1_kernel<<<dim3(gg, 2), 128>>>(W1, b1, N);          // 3: -> h1s (+zero agg2)
    scatter_kernel<true, 3><<<sg, 192>>>(src, dst, nullptr, E); // 4: h1s -> agg2
    gemm2_kernel<<<dim3(gg, 4), 128>>>(W2a, b2a, W2b, b2b, out, N); // 5
}